// round 13
// baseline (speedup 1.0000x reference)
#include <cuda_runtime.h>
#include <cstdint>

// ---------------------------------------------------------------------------
// P2G quadratic B-spline, 64^3 grid, B<=8 batches — tiled GATHER v2.
//
//  = R3's cell counting-sort + per-leg compile-time tap weights (proven)
//  + R6's SMEM halo-record staging (kills L2 MLP=1 latency stalls).
//  Divide fused into the gather; no scratch grid.
// ---------------------------------------------------------------------------

#define GRID_N    64
#define GRID_N3   (GRID_N * GRID_N * GRID_N)     // 262144
#define B_MAX     8
#define NBINS_MAX (B_MAX * GRID_N3)
#define REC_CAP   (2 * 1024 * 1024)

#define SCAN_BINS_PER_BLOCK 2048
#define SCAN_T              256
#define SCAN_PER            8

#define SM_REC_CAP 1600                          // halo mean ~1100

__device__ int    g_cnt[NBINS_MAX];
__device__ int    g_off[NBINS_MAX + 1];
__device__ int    g_cur[NBINS_MAX];
__device__ int    g_bsum[1024];
__device__ float4 g_rec[REC_CAP];                // (fx, fy, Xz, prob)

// ---------------------------------------------------------------------------

__global__ void k0_zero(int n4) {
    int4* p = reinterpret_cast<int4*>(g_cnt);
    for (int i = blockIdx.x * blockDim.x + threadIdx.x; i < n4;
         i += gridDim.x * blockDim.x)
        p[i] = make_int4(0, 0, 0, 0);
}

// ---------------------------------------------------------------------------

__device__ __forceinline__ int particle_key(const float* __restrict__ pos,
                                            const int* __restrict__ bidx,
                                            int i,
                                            float& Xx, float& Xy, float& Xz) {
    const float LO = 1e-5f, HI = 1.0f - 1e-5f;
    float px = fminf(fmaxf(pos[3 * i + 0], LO), HI);
    float py = fminf(fmaxf(pos[3 * i + 1], LO), HI);
    float pz = fminf(fmaxf(pos[3 * i + 2], LO), HI);
    Xx = px * 64.0f; Xy = py * 64.0f; Xz = pz * 64.0f;
    int bx = (int)Xx, by = (int)Xy, bz = (int)Xz;
    return (((bidx[i] << 6) | bx) << 6 | by) << 6 | bz;
}

// ---------------------------------------------------------------------------

__global__ void __launch_bounds__(256)
k1_hist(const float* __restrict__ pos, const int* __restrict__ bidx, int L) {
    int i = blockIdx.x * blockDim.x + threadIdx.x;
    if (i >= L) return;
    float Xx, Xy, Xz;
    int key = particle_key(pos, bidx, i, Xx, Xy, Xz);
    atomicAdd(&g_cnt[key], 1);
}

// ---------------------------------------------------------------------------

__global__ void k2a_partial(int nbins) {
    __shared__ int sm[SCAN_T];
    int b = blockIdx.x, t = threadIdx.x;
    int base = b * SCAN_BINS_PER_BLOCK + t * SCAN_PER;
    int s = 0;
    #pragma unroll
    for (int k = 0; k < SCAN_PER; k++) s += g_cnt[base + k];
    sm[t] = s;
    __syncthreads();
    for (int d = SCAN_T / 2; d > 0; d >>= 1) {
        if (t < d) sm[t] += sm[t + d];
        __syncthreads();
    }
    if (t == 0) g_bsum[b] = sm[0];
}

__global__ void k2b_scan(int nb, int nbins) {
    __shared__ int ws[32];
    int t = threadIdx.x;                 // 1024 threads
    int lane = t & 31, w = t >> 5;
    int v = (t < nb) ? g_bsum[t] : 0;
    int x = v;
    #pragma unroll
    for (int d = 1; d < 32; d <<= 1) {
        int y = __shfl_up_sync(0xFFFFFFFFu, x, d);
        if (lane >= d) x += y;
    }
    if (lane == 31) ws[w] = x;
    __syncthreads();
    if (w == 0) {
        int y = ws[lane];
        #pragma unroll
        for (int d = 1; d < 32; d <<= 1) {
            int z = __shfl_up_sync(0xFFFFFFFFu, y, d);
            if (lane >= d) y += z;
        }
        ws[lane] = y;
    }
    __syncthreads();
    int incl = x + ((w > 0) ? ws[w - 1] : 0);
    if (t < nb) g_bsum[t] = incl - v;            // exclusive
    if (t == nb - 1) g_off[nbins] = incl;
}

__global__ void k2c_offsets(int nbins) {
    __shared__ int sm[SCAN_T];
    int b = blockIdx.x, t = threadIdx.x;
    int base = b * SCAN_BINS_PER_BLOCK + t * SCAN_PER;
    int c[SCAN_PER], pre[SCAN_PER];
    int s = 0;
    #pragma unroll
    for (int k = 0; k < SCAN_PER; k++) {
        c[k] = g_cnt[base + k];
        pre[k] = s;
        s += c[k];
    }
    sm[t] = s;
    __syncthreads();
    for (int d = 1; d < SCAN_T; d <<= 1) {
        int a = (t >= d) ? sm[t - d] : 0;
        __syncthreads();
        sm[t] += a;
        __syncthreads();
    }
    int o = g_bsum[b] + (sm[t] - s);
    #pragma unroll
    for (int k = 0; k < SCAN_PER; k++) {
        int v = o + pre[k];
        g_off[base + k] = v;
        g_cur[base + k] = v;
    }
}

// ---------------------------------------------------------------------------

__global__ void __launch_bounds__(256)
k3_reorder(const float* __restrict__ pos, const float* __restrict__ prob,
           const int* __restrict__ bidx, int L) {
    int i = blockIdx.x * blockDim.x + threadIdx.x;
    if (i >= L) return;
    float Xx, Xy, Xz;
    int key = particle_key(pos, bidx, i, Xx, Xy, Xz);
    float fx = Xx - (float)((int)Xx);
    float fy = Xy - (float)((int)Xy);
    int r = atomicAdd(&g_cur[key], 1);
    g_rec[r] = make_float4(fx, fy, Xz, prob[i]);
}

// ---------------------------------------------------------------------------
// K4: tiled gather.  CTA = (b, 4x x-rows, 4y y-rows), 256 threads =
// 16 rows x 16 z-quads.  6x6 halo rows staged in SMEM; per-leg loops with
// compile-time tap indices (R3 math, proven correct).

__global__ void __launch_bounds__(256)
k4_gather(float* __restrict__ out) {
    __shared__ float4 s_rec[SM_REC_CAP];
    __shared__ int    s_off[6 * 6 * 65];     // [sx][iy][z0..64] global offsets
    __shared__ int    s_gstart[6], s_glen[6], s_delta[6];
    __shared__ int    s_ovf;

    int bid = blockIdx.x;
    int b   = bid >> 8;
    int tx0 = ((bid >> 4) & 15) << 2;
    int ty0 = (bid & 15) << 2;

    int tid = threadIdx.x;
    int lr  = tid >> 4;                      // 0..15 local row
    int lx  = lr >> 2, ly = lr & 3;
    int zq  = (tid & 15) << 2;               // 0,4,...,60

    int xx = tx0 + lx, yy = ty0 + ly;

    int ystart = max(ty0 - 1, 0);
    int yend   = min(ty0 + 4, 63);

    if (tid < 6) {
        int sx = tid;
        int x  = tx0 - 1 + sx;
        int gs = 0, len = 0;
        if ((unsigned)x < 64u) {
            int bin0 = (((b << 6) | x) << 6 | ystart) << 6;
            int bin1 = ((((b << 6) | x) << 6 | yend) << 6) + 64;
            gs  = g_off[bin0];
            len = g_off[bin1] - gs;
        }
        s_gstart[sx] = gs;
        s_glen[sx]   = len;
    }
    __syncthreads();

    if (tid == 0) {
        int acc = 0;
        #pragma unroll
        for (int sx = 0; sx < 6; sx++) {
            s_delta[sx] = acc - s_gstart[sx];
            acc += s_glen[sx];
        }
        s_ovf = (acc > SM_REC_CAP) ? 1 : 0;
    }
    __syncthreads();

    int ovf = s_ovf;

    // stage offset table
    for (int idx = tid; idx < 6 * 6 * 65; idx += 256) {
        int sx = idx / 390;
        int r  = idx - sx * 390;
        int iy = r / 65;
        int z  = r - iy * 65;
        int x  = tx0 - 1 + sx;
        int y  = ty0 - 1 + iy;
        int v  = 0;
        if ((unsigned)x < 64u && (unsigned)y < 64u)
            v = g_off[((((b << 6) | x) << 6 | y) << 6) + z];
        s_off[idx] = v;
    }

    // stage records
    if (!ovf) {
        #pragma unroll
        for (int sx = 0; sx < 6; sx++) {
            int len = s_glen[sx];
            int gs  = s_gstart[sx];
            int sb  = gs + s_delta[sx];
            for (int i = tid; i < len; i += 256)
                s_rec[sb + i] = g_rec[gs + i];
        }
    }
    __syncthreads();

    int blo  = max(zq - 1, 0);
    int bhi1 = min(zq + 5, 64);

    float aw[4] = {0.f, 0.f, 0.f, 0.f};
    float ap[4] = {0.f, 0.f, 0.f, 0.f};

    #pragma unroll
    for (int ox = -1; ox <= 1; ox++) {
        int nx = xx + ox;
        bool vx = ((unsigned)nx < 64u);
        int  sx = lx + ox + 1;
        const float4* rb = ovf ? (const float4*)g_rec
                               : (const float4*)(s_rec + s_delta[sx]);
        #pragma unroll
        for (int oy = -1; oy <= 1; oy++) {
            int ny = yy + oy;
            bool valid = vx && ((unsigned)ny < 64u);
            int  iy = ly + oy + 1;
            const int* op = s_off + (sx * 6 + iy) * 65;
            int j = op[blo];
            int e = valid ? op[bhi1] : j;
            const int TX = 1 - ox;               // compile-time after unroll
            const int TY = 1 - oy;
            for (; j < e; j++) {
                float4 r = rb[j];
                float wxp = (TX == 0) ? 0.5f * (1.f - r.x) * (1.f - r.x)
                          : (TX == 1) ? 0.75f - (r.x - 0.5f) * (r.x - 0.5f)
                                      : 0.5f * r.x * r.x;
                float wyp = (TY == 0) ? 0.5f * (1.f - r.y) * (1.f - r.y)
                          : (TY == 1) ? 0.75f - (r.y - 0.5f) * (r.y - 0.5f)
                                      : 0.5f * r.y * r.y;
                int   bz = (int)r.z;
                float fz = r.z - (float)bz;
                float c  = wxp * wyp;
                float a0 = c * 0.5f * (1.f - fz) * (1.f - fz);
                float a1 = c * (0.75f - (fz - 0.5f) * (fz - 0.5f));
                float a2 = c * 0.5f * fz * fz;
                int   tt = bz - zq;
                #pragma unroll
                for (int s4 = 0; s4 < 4; s4++) {
                    float ws = (tt == s4 + 1) ? a0
                             : (tt == s4)     ? a1
                             : (tt == s4 - 1) ? a2 : 0.f;
                    aw[s4] += ws;
                    ap[s4]  = fmaf(ws, r.w, ap[s4]);
                }
            }
        }
    }

    float4 o;
    o.x = ap[0] / (aw[0] + 1e-7f);
    o.y = ap[1] / (aw[1] + 1e-7f);
    o.z = ap[2] / (aw[2] + 1e-7f);
    o.w = ap[3] / (aw[3] + 1e-7f);
    int row = ((b << 6) | xx) << 6 | yy;
    *reinterpret_cast<float4*>(out + (row << 6) + zq) = o;
}

// ---------------------------------------------------------------------------

extern "C" void kernel_launch(void* const* d_in, const int* in_sizes, int n_in,
                              void* d_out, int out_size) {
    const float* pos  = (const float*)d_in[0];
    const float* prob = (const float*)d_in[1];
    const int*   bidx = (const int*)d_in[2];
    float*       out  = (float*)d_out;

    int L     = in_sizes[1];
    int B     = out_size / GRID_N3;
    int nbins = B * GRID_N3;
    int nb    = nbins / SCAN_BINS_PER_BLOCK;

    k0_zero<<<592, 256>>>(nbins / 4);
    k1_hist<<<(L + 255) / 256, 256>>>(pos, bidx, L);
    k2a_partial<<<nb, SCAN_T>>>(nbins);
    k2b_scan<<<1, 1024>>>(nb, nbins);
    k2c_offsets<<<nb, SCAN_T>>>(nbins);
    k3_reorder<<<(L + 255) / 256, 256>>>(pos, prob, bidx, L);
    k4_gather<<<B * 256, 256>>>(out);
}

// round 14
// speedup vs baseline: 1.4731x; 1.4731x over previous
#include <cuda_runtime.h>
#include <cstdint>

// ---------------------------------------------------------------------------
// P2G quadratic B-spline scatter, 64^3 grid, B<=8 batches.
//
//  - float2 scratch grid (w, w*prob), z-padded rows (68 cells, slot=z+2) so
//    the 3 z-taps always fit two aligned 16B windows -> 18 red.v4 lanes per
//    particle (measured floor: 1.29 cyc/lane, address-pattern independent).
//  - NO zero kernel: __device__ globals load zeroed; the finalize kernel
//    re-zeros every slot it (or the scatter) touched, restoring the all-zero
//    invariant for the next call. Deterministic: identical work every call.
// ---------------------------------------------------------------------------

#define GRID_N   64
#define GRID_N3  (GRID_N * GRID_N * GRID_N)
#define B_MAX    8
#define ROWLEN   68                          // 64 + 2 pad each side
#define NROWS    (B_MAX * GRID_N * GRID_N)   // 32768
#define NCELL_SCRATCH (NROWS * ROWLEN)

__device__ float2 g_acc[NCELL_SCRATCH];      // zero-initialized at load

// ---------------------------------------------------------------------------

__device__ __forceinline__ void red_add_v4(float2* addr,
                                           float a, float b, float c, float d) {
    asm volatile("red.global.add.v4.f32 [%0], {%1, %2, %3, %4};"
                 :: "l"(addr), "f"(a), "f"(b), "f"(c), "f"(d)
                 : "memory");
}

__global__ void __launch_bounds__(256)
p2g_scatter_kernel(const float* __restrict__ pos,
                   const float* __restrict__ prob,
                   const int*   __restrict__ bidx,
                   int L) {
    int i = blockIdx.x * blockDim.x + threadIdx.x;
    if (i >= L) return;

    const float EPS_CLIP = 1e-5f;
    const float HI       = 1.0f - 1e-5f;

    float px = fminf(fmaxf(pos[3 * i + 0], EPS_CLIP), HI);
    float py = fminf(fmaxf(pos[3 * i + 1], EPS_CLIP), HI);
    float pz = fminf(fmaxf(pos[3 * i + 2], EPS_CLIP), HI);

    float Xx = px * 64.0f;
    float Xy = py * 64.0f;
    float Xz = pz * 64.0f;

    int bx = (int)Xx;
    int by = (int)Xy;
    int bz = (int)Xz;

    float fx = Xx - (float)bx;
    float fy = Xy - (float)by;
    float fz = Xz - (float)bz;

    float wx[3], wy[3], wz0, wz1, wz2;
    wx[0] = 0.5f * (1.0f - fx) * (1.0f - fx);
    wx[1] = 0.75f - (fx - 0.5f) * (fx - 0.5f);
    wx[2] = 0.5f * fx * fx;
    wy[0] = 0.5f * (1.0f - fy) * (1.0f - fy);
    wy[1] = 0.75f - (fy - 0.5f) * (fy - 0.5f);
    wy[2] = 0.5f * fy * fy;
    wz0 = 0.5f * (1.0f - fz) * (1.0f - fz);
    wz1 = 0.75f - (fz - 0.5f) * (fz - 0.5f);
    wz2 = 0.5f * fz * fz;

    float p_val = prob[i];
    int   brow  = bidx[i] * (GRID_N * GRID_N);

    // shift 3 z-taps (slots bz+1..bz+3) into an aligned 4-cell window
    int zb    = bz + 1;          // in [1, 64]
    int shift = zb & 1;
    int a     = zb - shift;      // even, in [0, 64]; a+3 <= 67

    float z0 = shift ? 0.0f : wz0;
    float z1 = shift ? wz0  : wz1;
    float z2 = shift ? wz1  : wz2;
    float z3 = shift ? wz2  : 0.0f;
    float q0 = z0 * p_val;
    float q1 = z1 * p_val;
    float q2 = z2 * p_val;
    float q3 = z3 * p_val;

    #pragma unroll
    for (int ox = 0; ox < 3; ox++) {
        int tx = bx - 1 + ox;
        if ((unsigned)tx >= (unsigned)GRID_N) continue;
        int xrow = brow + tx * GRID_N;
        #pragma unroll
        for (int oy = 0; oy < 3; oy++) {
            int ty = by - 1 + oy;
            if ((unsigned)ty >= (unsigned)GRID_N) continue;
            float c = wx[ox] * wy[oy];
            float2* base = g_acc + (size_t)(xrow + ty) * ROWLEN + a;
            red_add_v4(base,     c * z0, c * q0, c * z1, c * q1);
            red_add_v4(base + 2, c * z2, c * q2, c * z3, c * q3);
        }
    }
}

// ---------------------------------------------------------------------------
// Finalize + reset: one thread per 4 output cells (float4 store).
// Each thread reads its 4 (w, wp) pairs, writes the divide result, and
// ZEROS those scratch slots. Threads handling the row ends also zero the
// 2+2 pad slots, restoring the all-zero invariant for the next call.

__global__ void __launch_bounds__(256)
p2g_finalize_kernel(float* __restrict__ out, int nquads) {
    int t = blockIdx.x * blockDim.x + threadIdx.x;
    if (t >= nquads) return;                 // nquads = B * 4096 * 16

    int row = t >> 4;                        // (b*64 + x)*64 + y
    int zq  = (t & 15) << 2;                 // 0,4,...,60

    float2* rp = g_acc + (size_t)row * ROWLEN;   // row base (slot 0)

    // slots zq+2 .. zq+5
    float4 lo = *reinterpret_cast<float4*>(rp + zq + 2);   // (w0,p0,w1,p1)
    float4 hi = *reinterpret_cast<float4*>(rp + zq + 4);   // (w2,p2,w3,p3)

    float4 o;
    o.x = lo.y / (lo.x + 1e-7f);
    o.y = lo.w / (lo.z + 1e-7f);
    o.z = hi.y / (hi.x + 1e-7f);
    o.w = hi.w / (hi.z + 1e-7f);
    *reinterpret_cast<float4*>(out + (row << 6) + zq) = o;

    // reset the slots we read
    const float4 zf4 = make_float4(0.f, 0.f, 0.f, 0.f);
    *reinterpret_cast<float4*>(rp + zq + 2) = zf4;
    *reinterpret_cast<float4*>(rp + zq + 4) = zf4;

    // pad slots: 0,1 (front) and 66,67 (back)
    if (zq == 0)
        *reinterpret_cast<float4*>(rp) = zf4;          // slots 0,1
    else if (zq == 60)
        *reinterpret_cast<float4*>(rp + 66) = zf4;     // slots 66,67
}

// ---------------------------------------------------------------------------

extern "C" void kernel_launch(void* const* d_in, const int* in_sizes, int n_in,
                              void* d_out, int out_size) {
    const float* pos  = (const float*)d_in[0];
    const float* prob = (const float*)d_in[1];
    const int*   bidx = (const int*)d_in[2];
    float*       out  = (float*)d_out;

    int L = in_sizes[1];                     // particle count (prob size)

    p2g_scatter_kernel<<<(L + 255) / 256, 256>>>(pos, prob, bidx, L);

    int nquads = out_size / 4;               // B * 4096 rows * 16 quads
    p2g_finalize_kernel<<<(nquads + 255) / 256, 256>>>(out, nquads);
}